// round 11
// baseline (speedup 1.0000x reference)
#include <cuda_runtime.h>

// CBOW negative-sampling loss, round 11: R8 main (proven) + PDL-overlapped reduce.
// ctx [B,CTX] i32, pos [B] i32, neg [B,NEG] i32, inW [V,D] f32, outW [V,D] f32 -> scalar f32.
#define VOCAB 50000
#define DIM   50
#define BATCH 131072
#define CTX   10
#define NEG   10

#define THREADS  128
#define WPB      (THREADS / 32)          // 4 samples per block
#define NBLOCKS  (BATCH / WPB)           // 32768
#define RED_B    512
#define RED_T    256                     // 512*256 = 131072 exact

#define RSTRIDE  28                      // 28 floats = 112B rows (16B aligned)

__device__ __align__(16) float g_wl[BATCH];   // per-sample loss
__device__ __align__(16) float g_red[RED_B];  // reduce partials
__device__ unsigned            g_cnt = 0;     // last-block counter (self-resetting)

__global__ __launch_bounds__(THREADS, 12)    // ~42 regs -> 1536 thr/SM (75% occ)
void cbow_main(const int* __restrict__ ctx,
               const int* __restrict__ pos,
               const int* __restrict__ neg,
               const float* __restrict__ inW,
               const float* __restrict__ outW)
{
    __shared__ int s_ctx[WPB * CTX];
    __shared__ int s_neg[WPB * NEG];
    __shared__ int s_pos[WPB];
    __shared__ __align__(16) float s_red[WPB][11 * RSTRIDE];

    const int tid  = threadIdx.x;
    const int lane = tid & 31;
    const int warp = tid >> 5;
    const int B0   = blockIdx.x * WPB;
    const unsigned FULL = 0xffffffffu;

    // ---- stage this block's indices, coalesced ----
    if (tid < WPB * CTX) s_ctx[tid] = __ldg(&ctx[B0 * CTX + tid]);
    if (tid < WPB * NEG) s_neg[tid] = __ldg(&neg[B0 * NEG + tid]);
    if (tid < WPB)       s_pos[tid] = __ldg(&pos[B0 + tid]);
    __syncthreads();

    const float2* __restrict__ inW2  = (const float2*)inW;
    const float2* __restrict__ outW2 = (const float2*)outW;
    const bool act = (lane < 25);            // 25 lanes x float2 = 50 dims

    // ---- context mean: 2 groups of 5 loads, fold immediately (low live regs) ----
    float2 cv = make_float2(0.f, 0.f);
    #pragma unroll
    for (int g = 0; g < 2; g++) {
        float2 t[5];
        #pragma unroll
        for (int c = 0; c < 5; c++) {
            int r = s_ctx[warp * CTX + g * 5 + c];
            t[c] = act ? __ldg(&inW2[r * 25 + lane]) : make_float2(0.f, 0.f);
        }
        #pragma unroll
        for (int c = 0; c < 5; c++) { cv.x += t[c].x; cv.y += t[c].y; }
    }
    cv.x *= (1.0f / CTX);
    cv.y *= (1.0f / CTX);

    // ---- 11 out_embed dots: 3 groups (4/4/3), fold to p[] immediately ----
    float p[NEG + 1];
    {
        float2 t[4];
        {
            int r = s_pos[warp];
            t[0] = act ? __ldg(&outW2[r * 25 + lane]) : make_float2(0.f, 0.f);
        }
        #pragma unroll
        for (int k = 0; k < 3; k++) {
            int r = s_neg[warp * NEG + k];
            t[k + 1] = act ? __ldg(&outW2[r * 25 + lane]) : make_float2(0.f, 0.f);
        }
        #pragma unroll
        for (int j = 0; j < 4; j++) p[j] = cv.x * t[j].x + cv.y * t[j].y;
    }
    {
        float2 t[4];
        #pragma unroll
        for (int k = 0; k < 4; k++) {
            int r = s_neg[warp * NEG + 3 + k];
            t[k] = act ? __ldg(&outW2[r * 25 + lane]) : make_float2(0.f, 0.f);
        }
        #pragma unroll
        for (int j = 0; j < 4; j++) p[4 + j] = cv.x * t[j].x + cv.y * t[j].y;
    }
    {
        float2 t[3];
        #pragma unroll
        for (int k = 0; k < 3; k++) {
            int r = s_neg[warp * NEG + 7 + k];
            t[k] = act ? __ldg(&outW2[r * 25 + lane]) : make_float2(0.f, 0.f);
        }
        #pragma unroll
        for (int j = 0; j < 3; j++) p[8 + j] = cv.x * t[j].x + cv.y * t[j].y;
    }

    // ---- smem transpose: lane j owns dot j ----
    if (act) {
        #pragma unroll
        for (int j = 0; j <= NEG; j++)
            s_red[warp][j * RSTRIDE + lane] = p[j];
    }
    __syncwarp();

    float term = 0.f;
    if (lane <= NEG) {
        const float* row = &s_red[warp][lane * RSTRIDE];
        float4 a = *(const float4*)(row);
        float4 b = *(const float4*)(row + 4);
        float4 c = *(const float4*)(row + 8);
        float4 d = *(const float4*)(row + 12);
        float4 e = *(const float4*)(row + 16);
        float4 f = *(const float4*)(row + 20);
        float s = ((a.x + a.y) + (a.z + a.w)) + ((b.x + b.y) + (b.z + b.w))
                + ((c.x + c.y) + (c.z + c.w)) + ((d.x + d.y) + (d.z + d.w))
                + ((e.x + e.y) + (e.z + e.w)) + ((f.x + f.y) + (f.z + f.w))
                + row[24];
        float arg = (lane == 0) ? s : -s;    // pos: +score, negs: -score
        float sg  = 1.0f / (1.0f + __expf(-arg));
        term = __logf(sg + 1e-10f);
    }
    #pragma unroll
    for (int o = 8; o > 0; o >>= 1)          // sum lanes 0..15 (11..15 zero)
        term += __shfl_xor_sync(FULL, term, o);

    // warp-granular retirement
    if (lane == 0) g_wl[B0 + warp] = term;

    // PDL trigger: all prior writes (incl. g_wl) are visible to the dependent
    // grid after its griddepcontrol.wait, per the PDL memory-ordering contract.
    asm volatile("griddepcontrol.launch_dependents;" ::: "memory");
}

__global__ __launch_bounds__(RED_T)
void cbow_reduce(float* __restrict__ out)
{
    // PDL: block until the primary grid's trigger (or completion) — overlaps
    // this grid's launch/setup with the primary's tail.
    asm volatile("griddepcontrol.wait;" ::: "memory");

    __shared__ float s[RED_T / 32];
    __shared__ bool  isLast;
    const int tid  = threadIdx.x;
    const int lane = tid & 31;
    const int warp = tid >> 5;
    const unsigned FULL = 0xffffffffu;

    float t = g_wl[blockIdx.x * RED_T + tid];
    #pragma unroll
    for (int o = 16; o > 0; o >>= 1)
        t += __shfl_xor_sync(FULL, t, o);
    if (lane == 0) s[warp] = t;
    __syncthreads();
    if (tid < 32) {
        float v = (tid < RED_T / 32) ? s[tid] : 0.f;
        #pragma unroll
        for (int o = 16; o > 0; o >>= 1)
            v += __shfl_xor_sync(FULL, v, o);
        if (tid == 0) {
            g_red[blockIdx.x] = v;
            __threadfence();
            unsigned old = atomicAdd(&g_cnt, 1u);
            isLast = (old == RED_B - 1);
        }
    }
    __syncthreads();

    if (isLast && tid < 32) {                 // deterministic fixed-order final sum
        float v = 0.f;
        #pragma unroll
        for (int i = 0; i < RED_B / 32; i++)
            v += __ldcg(&g_red[tid + i * 32]);
        #pragma unroll
        for (int o = 16; o > 0; o >>= 1)
            v += __shfl_xor_sync(FULL, v, o);
        if (tid == 0) {
            out[0] = -v / (float)BATCH;
            g_cnt = 0;                        // reset for next graph replay
        }
    }
}

extern "C" void kernel_launch(void* const* d_in, const int* in_sizes, int n_in,
                              void* d_out, int out_size)
{
    const int*   ctx  = (const int*)d_in[0];   // [B, CTX]
    const int*   pos  = (const int*)d_in[1];   // [B]
    const int*   neg  = (const int*)d_in[2];   // [B, NEG]
    const float* inW  = (const float*)d_in[3]; // [VOCAB, DIM]
    const float* outW = (const float*)d_in[4]; // [VOCAB, DIM]
    float* out = (float*)d_out;

    cbow_main<<<NBLOCKS, THREADS>>>(ctx, pos, neg, inW, outW);

    // Reduce with Programmatic Dependent Launch (overlap with main's tail).
    cudaLaunchConfig_t cfg = {};
    cfg.gridDim  = dim3(RED_B);
    cfg.blockDim = dim3(RED_T);
    cfg.dynamicSmemBytes = 0;
    cfg.stream = 0;                            // same (legacy default) stream as <<<>>>
    cudaLaunchAttribute attr[1];
    attr[0].id = cudaLaunchAttributeProgrammaticStreamSerialization;
    attr[0].val.programmaticStreamSerializationAllowed = 1;
    cfg.attrs = attr;
    cfg.numAttrs = 1;
    cudaLaunchKernelEx(&cfg, cbow_reduce, out);
}

// round 13
// speedup vs baseline: 1.4458x; 1.4458x over previous
#include <cuda_runtime.h>
#include <cuda_bf16.h>

// CBOW negative-sampling loss, round 12: bf16 table repack (7->4 sectors/gather)
// + proven R8 main/reduce structure.
#define VOCAB 50000
#define DIM   50
#define BATCH 131072
#define CTX   10
#define NEG   10

#define THREADS  128
#define WPB      (THREADS / 32)          // 4 samples per block
#define NBLOCKS  (BATCH / WPB)           // 32768
#define RED_B    256
#define RED_T    512                     // 256*512 = 131072 exact

#define RSTRIDE  28                      // 28 floats = 112B rows (16B aligned)

#define N4TAB    (VOCAB * DIM / 4)       // 625000 float4 per table
#define CVT_T    256
#define CVT_B    ((2 * N4TAB + CVT_T - 1) / CVT_T)

__device__ __align__(16) __nv_bfloat162 g_inB[VOCAB * 25];   // 5 MB bf16 in_embed
__device__ __align__(16) __nv_bfloat162 g_outB[VOCAB * 25];  // 5 MB bf16 out_embed
__device__ __align__(16) float g_wl[BATCH];   // per-sample loss
__device__ __align__(16) float g_red[RED_B];  // reduce partials
__device__ unsigned            g_cnt = 0;     // last-block counter (self-resetting)

// ---- table repack: fp32 -> bf16, both tables in one grid ----
__global__ __launch_bounds__(CVT_T)
void cbow_convert(const float4* __restrict__ inW4, const float4* __restrict__ outW4)
{
    int i = blockIdx.x * CVT_T + threadIdx.x;
    if (i >= 2 * N4TAB) return;
    float4 v;
    uint2* dst;
    if (i < N4TAB) {
        v   = __ldg(&inW4[i]);
        dst = reinterpret_cast<uint2*>(g_inB) + i;
    } else {
        int j = i - N4TAB;
        v   = __ldg(&outW4[j]);
        dst = reinterpret_cast<uint2*>(g_outB) + j;
    }
    __nv_bfloat162 lo = __floats2bfloat162_rn(v.x, v.y);
    __nv_bfloat162 hi = __floats2bfloat162_rn(v.z, v.w);
    *dst = make_uint2(*reinterpret_cast<unsigned*>(&lo),
                      *reinterpret_cast<unsigned*>(&hi));
}

__device__ __forceinline__ float2 bf2f(__nv_bfloat162 v) {
    return __bfloat1622float2(v);
}

__global__ __launch_bounds__(THREADS, 12)    // low regs -> 1536 thr/SM (75% occ)
void cbow_main(const int* __restrict__ ctx,
               const int* __restrict__ pos,
               const int* __restrict__ neg)
{
    __shared__ int s_ctx[WPB * CTX];
    __shared__ int s_neg[WPB * NEG];
    __shared__ int s_pos[WPB];
    __shared__ __align__(16) float s_red[WPB][11 * RSTRIDE];

    const int tid  = threadIdx.x;
    const int lane = tid & 31;
    const int warp = tid >> 5;
    const int B0   = blockIdx.x * WPB;
    const unsigned FULL = 0xffffffffu;

    // ---- stage this block's indices, coalesced ----
    if (tid < WPB * CTX) s_ctx[tid] = __ldg(&ctx[B0 * CTX + tid]);
    if (tid < WPB * NEG) s_neg[tid] = __ldg(&neg[B0 * NEG + tid]);
    if (tid < WPB)       s_pos[tid] = __ldg(&pos[B0 + tid]);
    __syncthreads();

    const bool act = (lane < 25);            // 25 lanes x bf16x2 = 50 dims
    const __nv_bfloat162 Z2 = __floats2bfloat162_rn(0.f, 0.f);

    // ---- context mean: 2 groups of 5 gathers (100B rows -> 4 sectors each) ----
    float2 cv = make_float2(0.f, 0.f);
    #pragma unroll
    for (int g = 0; g < 2; g++) {
        __nv_bfloat162 t[5];
        #pragma unroll
        for (int c = 0; c < 5; c++) {
            int r = s_ctx[warp * CTX + g * 5 + c];
            t[c] = act ? __ldg(&g_inB[r * 25 + lane]) : Z2;
        }
        #pragma unroll
        for (int c = 0; c < 5; c++) {
            float2 f = bf2f(t[c]);
            cv.x += f.x; cv.y += f.y;
        }
    }
    cv.x *= (1.0f / CTX);
    cv.y *= (1.0f / CTX);

    // ---- 11 out_embed dots: groups of 4/4/3, fold immediately ----
    float p[NEG + 1];
    {
        __nv_bfloat162 t[4];
        {
            int r = s_pos[warp];
            t[0] = act ? __ldg(&g_outB[r * 25 + lane]) : Z2;
        }
        #pragma unroll
        for (int k = 0; k < 3; k++) {
            int r = s_neg[warp * NEG + k];
            t[k + 1] = act ? __ldg(&g_outB[r * 25 + lane]) : Z2;
        }
        #pragma unroll
        for (int j = 0; j < 4; j++) {
            float2 f = bf2f(t[j]);
            p[j] = cv.x * f.x + cv.y * f.y;
        }
    }
    {
        __nv_bfloat162 t[4];
        #pragma unroll
        for (int k = 0; k < 4; k++) {
            int r = s_neg[warp * NEG + 3 + k];
            t[k] = act ? __ldg(&g_outB[r * 25 + lane]) : Z2;
        }
        #pragma unroll
        for (int j = 0; j < 4; j++) {
            float2 f = bf2f(t[j]);
            p[4 + j] = cv.x * f.x + cv.y * f.y;
        }
    }
    {
        __nv_bfloat162 t[3];
        #pragma unroll
        for (int k = 0; k < 3; k++) {
            int r = s_neg[warp * NEG + 7 + k];
            t[k] = act ? __ldg(&g_outB[r * 25 + lane]) : Z2;
        }
        #pragma unroll
        for (int j = 0; j < 3; j++) {
            float2 f = bf2f(t[j]);
            p[8 + j] = cv.x * f.x + cv.y * f.y;
        }
    }

    // ---- smem transpose: lane j owns dot j ----
    if (act) {
        #pragma unroll
        for (int j = 0; j <= NEG; j++)
            s_red[warp][j * RSTRIDE + lane] = p[j];
    }
    __syncwarp();

    float term = 0.f;
    if (lane <= NEG) {
        const float* row = &s_red[warp][lane * RSTRIDE];
        float4 a = *(const float4*)(row);
        float4 b = *(const float4*)(row + 4);
        float4 c = *(const float4*)(row + 8);
        float4 d = *(const float4*)(row + 12);
        float4 e = *(const float4*)(row + 16);
        float4 f = *(const float4*)(row + 20);
        float s = ((a.x + a.y) + (a.z + a.w)) + ((b.x + b.y) + (b.z + b.w))
                + ((c.x + c.y) + (c.z + c.w)) + ((d.x + d.y) + (d.z + d.w))
                + ((e.x + e.y) + (e.z + e.w)) + ((f.x + f.y) + (f.z + f.w))
                + row[24];
        float arg = (lane == 0) ? s : -s;    // pos: +score, negs: -score
        float sg  = 1.0f / (1.0f + __expf(-arg));
        term = __logf(sg + 1e-10f);
    }
    #pragma unroll
    for (int o = 8; o > 0; o >>= 1)          // sum lanes 0..15 (11..15 zero)
        term += __shfl_xor_sync(FULL, term, o);

    // warp-granular retirement
    if (lane == 0) g_wl[B0 + warp] = term;
}

__global__ __launch_bounds__(RED_T)
void cbow_reduce(float* __restrict__ out)
{
    __shared__ float s[RED_T / 32];
    __shared__ bool  isLast;
    const int tid  = threadIdx.x;
    const int lane = tid & 31;
    const int warp = tid >> 5;
    const unsigned FULL = 0xffffffffu;

    float t = g_wl[blockIdx.x * RED_T + tid];
    #pragma unroll
    for (int o = 16; o > 0; o >>= 1)
        t += __shfl_xor_sync(FULL, t, o);
    if (lane == 0) s[warp] = t;
    __syncthreads();
    if (tid < 32) {
        float v = (tid < RED_T / 32) ? s[tid] : 0.f;
        #pragma unroll
        for (int o = 16; o > 0; o >>= 1)
            v += __shfl_xor_sync(FULL, v, o);
        if (tid == 0) {
            g_red[blockIdx.x] = v;
            __threadfence();
            unsigned old = atomicAdd(&g_cnt, 1u);
            isLast = (old == RED_B - 1);
        }
    }
    __syncthreads();

    if (isLast && tid < 32) {                 // deterministic fixed-order final sum
        float v = 0.f;
        #pragma unroll
        for (int i = 0; i < RED_B / 32; i++)
            v += __ldcg(&g_red[tid + i * 32]);
        #pragma unroll
        for (int o = 16; o > 0; o >>= 1)
            v += __shfl_xor_sync(FULL, v, o);
        if (tid == 0) {
            out[0] = -v / (float)BATCH;
            g_cnt = 0;                        // reset for next graph replay
        }
    }
}

extern "C" void kernel_launch(void* const* d_in, const int* in_sizes, int n_in,
                              void* d_out, int out_size)
{
    const int*   ctx  = (const int*)d_in[0];   // [B, CTX]
    const int*   pos  = (const int*)d_in[1];   // [B]
    const int*   neg  = (const int*)d_in[2];   // [B, NEG]
    const float* inW  = (const float*)d_in[3]; // [VOCAB, DIM]
    const float* outW = (const float*)d_in[4]; // [VOCAB, DIM]
    float* out = (float*)d_out;

    cbow_convert<<<CVT_B, CVT_T>>>((const float4*)inW, (const float4*)outW);
    cbow_main<<<NBLOCKS, THREADS>>>(ctx, pos, neg);
    cbow_reduce<<<RED_B, RED_T>>>(out);
}